// round 10
// baseline (speedup 1.0000x reference)
#include <cuda_runtime.h>
#include <cuda_bf16.h>
#include <math.h>
#include <stdint.h>

// Problem constants
#define E_      8
#define S_      512
#define DIM_    1024
#define DFF_    2730
#define DFF2_   5460
#define VOCAB_  32000
#define NPAIR   1024   // S_ * 2

// ------------------------- device scratch (device-code access only) ----------
__device__ int   g_cnt[E_];
__device__ int   g_rows[E_][NPAIR];
__device__ int   g_eid[NPAIR];
__device__ float g_gate[NPAIR];
__device__ float g_lse[NPAIR];
__device__ float g_up[(size_t)NPAIR * DFF2_];
__device__ float g_h1[(size_t)NPAIR * DFF_];
__device__ float g_h2[(size_t)NPAIR * DIM_];
__device__ float g_logits[(size_t)NPAIR * VOCAB_];

// ------------------------- PTX helpers (sm_80-era, plain sm_103-safe) --------
__device__ __forceinline__ uint32_t smem_u32(const void* p) {
    uint32_t a;
    asm("{ .reg .u64 t; cvta.to.shared.u64 t, %1; cvt.u32.u64 %0, t; }"
        : "=r"(a) : "l"(p));
    return a;
}
#define CPA16(dst, src) \
    asm volatile("cp.async.cg.shared.global [%0], [%1], 16;" :: "r"(dst), "l"(src))
#define CPA8(dst, src) \
    asm volatile("cp.async.ca.shared.global [%0], [%1], 8;" :: "r"(dst), "l"(src))
#define CPA_COMMIT() asm volatile("cp.async.commit_group;" ::: "memory")
#define CPA_WAIT(n)  asm volatile("cp.async.wait_group %0;" :: "n"(n) : "memory")

// pack two fp32 -> bf16x2 (lo = lower-k element in low 16 bits)
__device__ __forceinline__ uint32_t packbf(float lo, float hi) {
    uint32_t r;
    asm("cvt.rn.bf16x2.f32 %0, %1, %2;" : "=r"(r) : "f"(hi), "f"(lo));
    return r;
}
__device__ __forceinline__ void mma_bf16(float* d, const uint32_t* a, const uint32_t* b) {
    asm volatile(
        "mma.sync.aligned.m16n8k16.row.col.f32.bf16.bf16.f32 "
        "{%0,%1,%2,%3}, {%4,%5,%6,%7}, {%8,%9}, {%0,%1,%2,%3};"
        : "+f"(d[0]), "+f"(d[1]), "+f"(d[2]), "+f"(d[3])
        : "r"(a[0]), "r"(a[1]), "r"(a[2]), "r"(a[3]), "r"(b[0]), "r"(b[1]));
}

// ------------------------- router (exact fp32) -------------------------
__global__ void router_kernel(const float* __restrict__ x,
                              const float* __restrict__ Wr) {
    int s = blockIdx.x;
    const float* xr = x + (size_t)s * DIM_;
    float acc[E_];
#pragma unroll
    for (int e = 0; e < E_; e++) acc[e] = 0.f;
    for (int d = threadIdx.x; d < DIM_; d += blockDim.x) {
        float xv = xr[d];
#pragma unroll
        for (int e = 0; e < E_; e++) acc[e] = fmaf(xv, Wr[e * DIM_ + d], acc[e]);
    }
    __shared__ float red[256];
    __shared__ float score[E_];
#pragma unroll
    for (int e = 0; e < E_; e++) {
        red[threadIdx.x] = acc[e];
        __syncthreads();
        for (int st = 128; st > 0; st >>= 1) {
            if (threadIdx.x < st) red[threadIdx.x] += red[threadIdx.x + st];
            __syncthreads();
        }
        if (threadIdx.x == 0) score[e] = red[0];
        __syncthreads();
    }
    if (threadIdx.x == 0) {
        int i0 = 0; float s0 = score[0];
        for (int e = 1; e < E_; e++) if (score[e] > s0) { s0 = score[e]; i0 = e; }
        int i1 = -1; float s1 = -INFINITY;
        for (int e = 0; e < E_; e++) {
            if (e == i0) continue;
            if (score[e] > s1) { s1 = score[e]; i1 = e; }
        }
        float m   = fmaxf(s0, s1);
        float lse = m + logf(expf(s0 - m) + expf(s1 - m));
        int p0 = 2 * s, p1 = 2 * s + 1;
        g_gate[p0] = s0 - lse;  g_gate[p1] = s1 - lse;
        g_eid[p0]  = i0;        g_eid[p1]  = i1;
    }
}

__global__ void group_kernel() {
    int w    = threadIdx.x / 32;
    int lane = threadIdx.x % 32;
    if (w >= E_) return;
    int count = 0;
    for (int base = 0; base < NPAIR; base += 32) {
        int p  = base + lane;
        int id = g_eid[p];
        unsigned mask = __ballot_sync(0xffffffffu, id == w);
        if (id == w) {
            int pos = count + __popc(mask & ((1u << lane) - 1u));
            g_rows[w][pos] = p;
        }
        count += __popc(mask);
    }
    if (lane == 0) g_cnt[w] = count;
}

// ------------------------- bf16 mma.sync grouped GEMM, 4-stage pipeline ------
// Block tile 128x128, BK=32, 8 warps (2x4), warp tile 64x32, m16n8k16 bf16.
// 4-stage cp.async ring keeps 3 chunks in flight (hides DRAM latency).
// a_sel: 0=ext(x) 1=g_h1 2=g_h2 ; out_sel: 0=g_up 1=g_h2 2=g_logits
#define TM 128
#define TN 128
#define BK 32
#define NSTAGE 4
#define LDS_STRIDE 40
#define A_TILE_F (128 * LDS_STRIDE)
#define B_TILE_F (128 * LDS_STRIDE)
#define STAGE_F  (A_TILE_F + B_TILE_F)
#define GEMM_SMEM (NSTAGE * STAGE_F * 4)     // 163,840 B

__global__ __launch_bounds__(256, 1)
void gemm_tc_kernel(const float* __restrict__ Aext,
                    const float* __restrict__ Bw,
                    const float* __restrict__ bias,
                    const float* __restrict__ resid,
                    int a_sel, int out_sel,
                    int Kdim, int Nt, int row_shift) {
    extern __shared__ float sm[];
    const float* A   = (a_sel == 0) ? Aext : (a_sel == 1 ? g_h1 : g_h2);
    float*       Out = (out_sel == 0) ? g_up : (out_sel == 1 ? g_h2 : g_logits);

    int e   = blockIdx.z;
    int cnt = g_cnt[e];
    int m0  = blockIdx.y * TM;
    if (m0 >= cnt) return;
    int n0  = blockIdx.x * TN;

    const float* Bexp = Bw + (size_t)e * Nt * Kdim;
    const int*   rows = g_rows[e];
    int tid = threadIdx.x, wid = tid >> 5, lane = tid & 31;

    const bool f4 = ((Kdim & 3) == 0);
    const int  nch = (Kdim + BK - 1) / BK;

    // stage s: A at sm + s*STAGE_F, B at + A_TILE_F
    auto load_tile = [&](int i, int s) {
        int k0 = i * BK;
        float* Ab = sm + s * STAGE_F;
        float* Bb = Ab + A_TILE_F;
        uint32_t Au = smem_u32(Ab), Bu = smem_u32(Bb);
        if (f4) {
            // A: 128 rows x 8 float4 (1024 units / 256 thr = 4 each)
            for (int u = tid; u < 128 * 8; u += 256) {
                int r = u >> 3, c = u & 7, kg = k0 + c * 4;
                int gm = m0 + r;
                uint32_t dA = Au + (uint32_t)(r * LDS_STRIDE + c * 4) * 4u;
                if (gm < cnt) {
                    int pr = rows[gm];
                    int rr = row_shift ? (pr >> 1) : pr;
                    CPA16(dA, A + (size_t)rr * Kdim + kg);
                } else {
                    *(float4*)(Ab + r * LDS_STRIDE + c * 4) = make_float4(0, 0, 0, 0);
                }
            }
            for (int u = tid; u < 128 * 8; u += 256) {
                int r = u >> 3, c = u & 7, kg = k0 + c * 4;
                int gn = n0 + r;
                uint32_t dB = Bu + (uint32_t)(r * LDS_STRIDE + c * 4) * 4u;
                if (gn < Nt) {
                    CPA16(dB, Bexp + (size_t)gn * Kdim + kg);
                } else {
                    *(float4*)(Bb + r * LDS_STRIDE + c * 4) = make_float4(0, 0, 0, 0);
                }
            }
        } else {
            // 8B granules (K=2730; rows only 8B-aligned)
            for (int u = tid; u < 128 * 16; u += 256) {
                int r = u >> 4, c = u & 15, kg = k0 + c * 2;
                int gm = m0 + r;
                uint32_t dA = Au + (uint32_t)(r * LDS_STRIDE + c * 2) * 4u;
                if (gm < cnt && kg < Kdim) {
                    int pr = rows[gm];
                    int rr = row_shift ? (pr >> 1) : pr;
                    CPA8(dA, A + (size_t)rr * Kdim + kg);
                } else {
                    *(float2*)(sm + s * STAGE_F + r * LDS_STRIDE + c * 2) = make_float2(0, 0);
                }
            }
            for (int u = tid; u < 128 * 16; u += 256) {
                int r = u >> 4, c = u & 15, kg = k0 + c * 2;
                int gn = n0 + r;
                uint32_t dB = Bu + (uint32_t)(r * LDS_STRIDE + c * 2) * 4u;
                if (gn < Nt && kg < Kdim) {
                    CPA8(dB, Bexp + (size_t)gn * Kdim + kg);
                } else {
                    *(float2*)(sm + s * STAGE_F + A_TILE_F + r * LDS_STRIDE + c * 2) = make_float2(0, 0);
                }
            }
        }
    };

    // warp layout: 2 (m) x 4 (n); warp tile 64 x 32
    int wy = wid >> 2, wx = wid & 3;
    int mw = wy * 64, nw = wx * 32;
    int lr = lane >> 2, lc = lane & 3;

    float acc[4][4][4];
#pragma unroll
    for (int i = 0; i < 4; i++)
#pragma unroll
        for (int j = 0; j < 4; j++)
#pragma unroll
            for (int q = 0; q < 4; q++) acc[i][j][q] = 0.f;

    // prologue: fill NSTAGE-1 stages
#pragma unroll
    for (int s = 0; s < NSTAGE - 1; s++) {
        if (s < nch) load_tile(s, s);
        CPA_COMMIT();
    }

    for (int it = 0; it < nch; it++) {
        int pre = it + NSTAGE - 1;
        if (pre < nch) load_tile(pre, pre % NSTAGE);
        CPA_COMMIT();
        CPA_WAIT(NSTAGE - 1);
        __syncthreads();

        const float* As = sm + (it % NSTAGE) * STAGE_F;
        const float* Bs = As + A_TILE_F;
#pragma unroll
        for (int ks = 0; ks < BK; ks += 16) {
            uint32_t af[4][4], bf[4][2];
#pragma unroll
            for (int mt = 0; mt < 4; mt++) {
                const float* p = As + (mw + mt * 16 + lr) * LDS_STRIDE + ks + 2 * lc;
                float2 v0 = *(const float2*)(p);
                float2 v1 = *(const float2*)(p + 8 * LDS_STRIDE);
                float2 v2 = *(const float2*)(p + 8);
                float2 v3 = *(const float2*)(p + 8 * LDS_STRIDE + 8);
                af[mt][0] = packbf(v0.x, v0.y);
                af[mt][1] = packbf(v1.x, v1.y);
                af[mt][2] = packbf(v2.x, v2.y);
                af[mt][3] = packbf(v3.x, v3.y);
            }
#pragma unroll
            for (int nt = 0; nt < 4; nt++) {
                const float* q = Bs + (nw + nt * 8 + lr) * LDS_STRIDE + ks + 2 * lc;
                float2 u0 = *(const float2*)(q);
                float2 u1 = *(const float2*)(q + 8);
                bf[nt][0] = packbf(u0.x, u0.y);
                bf[nt][1] = packbf(u1.x, u1.y);
            }
#pragma unroll
            for (int mt = 0; mt < 4; mt++)
#pragma unroll
                for (int nt = 0; nt < 4; nt++)
                    mma_bf16(acc[mt][nt], af[mt], bf[nt]);
        }
        __syncthreads();
    }

    // ---- epilogue: scatter with gather row-mapping, bias, residual ----
    const float* bb = bias ? bias + (size_t)e * Nt : nullptr;
#pragma unroll
    for (int mt = 0; mt < 4; mt++) {
#pragma unroll
        for (int half = 0; half < 2; half++) {
            int rg = m0 + mw + mt * 16 + lr + half * 8;
            if (rg >= cnt) continue;
            int pair = rows[rg];
            size_t obase = (size_t)pair * Nt;
            const float* rr = resid ? resid + (size_t)(pair >> 1) * Nt : nullptr;
#pragma unroll
            for (int nt = 0; nt < 4; nt++) {
                int cg = n0 + nw + nt * 8 + 2 * lc;
#pragma unroll
                for (int q = 0; q < 2; q++) {
                    int col = cg + q;
                    if (col >= Nt) continue;
                    float v = acc[mt][nt][half * 2 + q];
                    if (bb) v += bb[col];
                    if (rr) v += rr[col];
                    Out[obase + col] = v;
                }
            }
        }
    }
}

// ------------------------- SwiGLU (exact GELU) -------------------------
__global__ void swiglu_kernel() {
    size_t i = (size_t)blockIdx.x * blockDim.x + threadIdx.x;
    const size_t total = (size_t)NPAIR * DFF_;
    if (i >= total) return;
    size_t p = i / DFF_;
    int    j = (int)(i % DFF_);
    float h = g_up[p * DFF2_ + j];
    float g = g_up[p * DFF2_ + DFF_ + j];
    float ge = 0.5f * g * (1.f + erff(g * 0.70710678118654752440f));
    g_h1[i] = h * ge;
}

// ------------------------- online logsumexp over vocab (single pass) ---------
__global__ void lse_kernel() {
    int p = blockIdx.x;
    const float* l = g_logits + (size_t)p * VOCAB_;
    int tid = threadIdx.x;
    float m = -INFINITY, s = 0.f;
    for (int v = tid; v < VOCAB_; v += 256) {
        float xv = l[v];
        if (xv > m) { s = s * expf(m - xv) + 1.f; m = xv; }
        else        { s += expf(xv - m); }
    }
    __shared__ float rm[256], rs[256];
    rm[tid] = m; rs[tid] = s;
    __syncthreads();
    for (int st = 128; st > 0; st >>= 1) {
        if (tid < st) {
            float m2 = rm[tid + st], s2 = rs[tid + st];
            float mm = fmaxf(rm[tid], m2);
            rs[tid] = rs[tid] * expf(rm[tid] - mm) + s2 * expf(m2 - mm);
            rm[tid] = mm;
        }
        __syncthreads();
    }
    if (tid == 0) g_lse[p] = rm[0] + logf(rs[0]);
}

// ------------------------- combine two experts per token ---------------------
__global__ void combine_kernel(float* __restrict__ out) {
    size_t idx = (size_t)blockIdx.x * blockDim.x + threadIdx.x;
    const size_t total = (size_t)S_ * VOCAB_;
    if (idx >= total) return;
    int s = (int)(idx / VOCAB_);
    int v = (int)(idx % VOCAB_);
    int p0 = 2 * s, p1 = 2 * s + 1;
    float a0 = g_logits[(size_t)p0 * VOCAB_ + v] + g_gate[p0] - g_lse[p0];
    float a1 = g_logits[(size_t)p1 * VOCAB_ + v] + g_gate[p1] - g_lse[p1];
    float m = fmaxf(a0, a1);
    out[idx] = m + logf(expf(a0 - m) + expf(a1 - m));
}

// ------------------------- launch -------------------------
extern "C" void kernel_launch(void* const* d_in, const int* in_sizes, int n_in,
                              void* d_out, int out_size) {
    const float *x = nullptr, *Wr = nullptr, *Wup = nullptr,
                *bup = nullptr, *Wdown = nullptr, *Wproj = nullptr;
    for (int i = 0; i < n_in; i++) {
        const float* p = (const float*)d_in[i];
        switch (in_sizes[i]) {
            case S_ * DIM_:            x     = p; break;
            case E_ * DIM_:            Wr    = p; break;
            case E_ * DFF2_ * DIM_:    Wup   = p; break;
            case E_ * DFF2_:           bup   = p; break;
            case E_ * DIM_ * DFF_:     Wdown = p; break;
            case E_ * VOCAB_ * DIM_:   Wproj = p; break;
        }
    }
    if (!x)     x     = (const float*)d_in[0];
    if (!Wr)    Wr    = (const float*)d_in[1];
    if (!Wup)   Wup   = (const float*)d_in[2];
    if (!bup)   bup   = (const float*)d_in[3];
    if (!Wdown) Wdown = (const float*)d_in[4];
    if (!Wproj) Wproj = (const float*)d_in[5];
    float* out = (float*)d_out;

    cudaFuncSetAttribute(gemm_tc_kernel,
                         cudaFuncAttributeMaxDynamicSharedMemorySize, GEMM_SMEM);

    router_kernel<<<S_, 256>>>(x, Wr);
    group_kernel<<<1, 256>>>();

    {   // up: g_up = x_g @ Wup[e]^T + bup[e]
        dim3 grid((DFF2_ + TN - 1) / TN, (NPAIR + TM - 1) / TM, E_);
        gemm_tc_kernel<<<grid, 256, GEMM_SMEM>>>(x, Wup, bup, nullptr,
                                                 0, 0, DIM_, DFF2_, 1);
    }
    {   // SwiGLU
        size_t total = (size_t)NPAIR * DFF_;
        swiglu_kernel<<<(int)((total + 255) / 256), 256>>>();
    }
    {   // down + residual: g_h2 = g_h1 @ Wdown[e]^T + x
        dim3 grid((DIM_ + TN - 1) / TN, (NPAIR + TM - 1) / TM, E_);
        gemm_tc_kernel<<<grid, 256, GEMM_SMEM>>>(nullptr, Wdown, nullptr, x,
                                                 1, 1, DFF_, DIM_, 0);
    }
    {   // proj: g_logits = g_h2 @ Wproj[e]^T
        dim3 grid((VOCAB_ + TN - 1) / TN, (NPAIR + TM - 1) / TM, E_);
        gemm_tc_kernel<<<grid, 256, GEMM_SMEM>>>(nullptr, Wproj, nullptr, nullptr,
                                                 2, 2, DIM_, VOCAB_, 0);
    }
    lse_kernel<<<NPAIR, 256>>>();
    {
        size_t total = (size_t)S_ * VOCAB_;
        combine_kernel<<<(int)((total + 255) / 256), 256>>>(out);
    }
}

// round 11
// speedup vs baseline: 1.2106x; 1.2106x over previous
#include <cuda_runtime.h>
#include <cuda_bf16.h>
#include <math.h>
#include <stdint.h>

// Problem constants
#define E_      8
#define S_      512
#define DIM_    1024
#define DFF_    2730
#define DFF2_   5460
#define VOCAB_  32000
#define NPAIR   1024   // S_ * 2

// ------------------------- device scratch (device-code access only) ----------
__device__ int   g_cnt[E_];
__device__ int   g_rows[E_][NPAIR];
__device__ int   g_eid[NPAIR];
__device__ float g_gate[NPAIR];
__device__ float g_lse[NPAIR];
__device__ float g_up[(size_t)NPAIR * DFF2_];
__device__ float g_h1[(size_t)NPAIR * DFF_];
__device__ float g_h2[(size_t)NPAIR * DIM_];
__device__ float g_logits[(size_t)NPAIR * VOCAB_];

// ------------------------- PTX helpers (sm_80-era, plain sm_103-safe) --------
__device__ __forceinline__ uint32_t smem_u32(const void* p) {
    uint32_t a;
    asm("{ .reg .u64 t; cvta.to.shared.u64 t, %1; cvt.u32.u64 %0, t; }"
        : "=r"(a) : "l"(p));
    return a;
}
#define CPA16(dst, src) \
    asm volatile("cp.async.cg.shared.global [%0], [%1], 16;" :: "r"(dst), "l"(src))
#define CPA8(dst, src) \
    asm volatile("cp.async.ca.shared.global [%0], [%1], 8;" :: "r"(dst), "l"(src))
#define CPA_COMMIT() asm volatile("cp.async.commit_group;" ::: "memory")
#define CPA_WAIT(n)  asm volatile("cp.async.wait_group %0;" :: "n"(n) : "memory")

// pack two fp32 -> bf16x2 (lo = lower-k element in low 16 bits)
__device__ __forceinline__ uint32_t packbf(float lo, float hi) {
    uint32_t r;
    asm("cvt.rn.bf16x2.f32 %0, %1, %2;" : "=r"(r) : "f"(hi), "f"(lo));
    return r;
}
__device__ __forceinline__ void mma_bf16(float* d, const uint32_t* a, const uint32_t* b) {
    asm volatile(
        "mma.sync.aligned.m16n8k16.row.col.f32.bf16.bf16.f32 "
        "{%0,%1,%2,%3}, {%4,%5,%6,%7}, {%8,%9}, {%0,%1,%2,%3};"
        : "+f"(d[0]), "+f"(d[1]), "+f"(d[2]), "+f"(d[3])
        : "r"(a[0]), "r"(a[1]), "r"(a[2]), "r"(a[3]), "r"(b[0]), "r"(b[1]));
}

// ------------------------- router (exact fp32) -------------------------
__global__ void router_kernel(const float* __restrict__ x,
                              const float* __restrict__ Wr) {
    int s = blockIdx.x;
    const float* xr = x + (size_t)s * DIM_;
    float acc[E_];
#pragma unroll
    for (int e = 0; e < E_; e++) acc[e] = 0.f;
    for (int d = threadIdx.x; d < DIM_; d += blockDim.x) {
        float xv = xr[d];
#pragma unroll
        for (int e = 0; e < E_; e++) acc[e] = fmaf(xv, Wr[e * DIM_ + d], acc[e]);
    }
    __shared__ float red[256];
    __shared__ float score[E_];
#pragma unroll
    for (int e = 0; e < E_; e++) {
        red[threadIdx.x] = acc[e];
        __syncthreads();
        for (int st = 128; st > 0; st >>= 1) {
            if (threadIdx.x < st) red[threadIdx.x] += red[threadIdx.x + st];
            __syncthreads();
        }
        if (threadIdx.x == 0) score[e] = red[0];
        __syncthreads();
    }
    if (threadIdx.x == 0) {
        int i0 = 0; float s0 = score[0];
        for (int e = 1; e < E_; e++) if (score[e] > s0) { s0 = score[e]; i0 = e; }
        int i1 = -1; float s1 = -INFINITY;
        for (int e = 0; e < E_; e++) {
            if (e == i0) continue;
            if (score[e] > s1) { s1 = score[e]; i1 = e; }
        }
        float m   = fmaxf(s0, s1);
        float lse = m + logf(expf(s0 - m) + expf(s1 - m));
        int p0 = 2 * s, p1 = 2 * s + 1;
        g_gate[p0] = s0 - lse;  g_gate[p1] = s1 - lse;
        g_eid[p0]  = i0;        g_eid[p1]  = i1;
    }
}

__global__ void group_kernel() {
    int w    = threadIdx.x / 32;
    int lane = threadIdx.x % 32;
    if (w >= E_) return;
    int count = 0;
    for (int base = 0; base < NPAIR; base += 32) {
        int p  = base + lane;
        int id = g_eid[p];
        unsigned mask = __ballot_sync(0xffffffffu, id == w);
        if (id == w) {
            int pos = count + __popc(mask & ((1u << lane) - 1u));
            g_rows[w][pos] = p;
        }
        count += __popc(mask);
    }
    if (lane == 0) g_cnt[w] = count;
}

// ------------------------- bf16 mma.sync grouped GEMM, 3-stage ring ----------
// Block tile 128x256, BK=32, 8 warps (2x4), warp tile 64x64, m16n8k16 bf16.
// Single barrier per chunk; prefetch issued right after the barrier; 2 chunks
// (~96KB) kept in flight to cover DRAM latency at NAT clocks.
// a_sel: 0=ext(x) 1=g_h1 2=g_h2 ; out_sel: 0=g_up 1=g_h2 2=g_logits
#define TM 128
#define TN 256
#define BK 32
#define NSTAGE 3
#define LDS_STRIDE 40
#define A_TILE_F (128 * LDS_STRIDE)
#define B_TILE_F (256 * LDS_STRIDE)
#define STAGE_F  (A_TILE_F + B_TILE_F)
#define GEMM_SMEM (NSTAGE * STAGE_F * 4)   // 184,320 B

__global__ __launch_bounds__(256, 1)
void gemm_tc_kernel(const float* __restrict__ Aext,
                    const float* __restrict__ Bw,
                    const float* __restrict__ bias,
                    const float* __restrict__ resid,
                    int a_sel, int out_sel,
                    int Kdim, int Nt, int row_shift) {
    extern __shared__ float sm[];
    const float* A   = (a_sel == 0) ? Aext : (a_sel == 1 ? g_h1 : g_h2);
    float*       Out = (out_sel == 0) ? g_up : (out_sel == 1 ? g_h2 : g_logits);

    int e   = blockIdx.z;
    int cnt = g_cnt[e];
    int m0  = blockIdx.y * TM;
    if (m0 >= cnt) return;
    int n0  = blockIdx.x * TN;

    const float* Bexp = Bw + (size_t)e * Nt * Kdim;
    const int*   rows = g_rows[e];
    int tid = threadIdx.x, wid = tid >> 5, lane = tid & 31;

    const bool f4 = ((Kdim & 3) == 0);
    const int  nch = (Kdim + BK - 1) / BK;

    auto load_tile = [&](int i, int s) {
        int k0 = i * BK;
        float* Ab = sm + s * STAGE_F;
        float* Bb = Ab + A_TILE_F;
        uint32_t Au = smem_u32(Ab), Bu = smem_u32(Bb);
        if (f4) {
            for (int u = tid; u < 128 * 8; u += 256) {
                int r = u >> 3, c = u & 7, kg = k0 + c * 4;
                int gm = m0 + r;
                uint32_t dA = Au + (uint32_t)(r * LDS_STRIDE + c * 4) * 4u;
                if (gm < cnt) {
                    int pr = rows[gm];
                    int rr = row_shift ? (pr >> 1) : pr;
                    CPA16(dA, A + (size_t)rr * Kdim + kg);
                } else {
                    *(float4*)(Ab + r * LDS_STRIDE + c * 4) = make_float4(0, 0, 0, 0);
                }
            }
            for (int u = tid; u < 256 * 8; u += 256) {
                int r = u >> 3, c = u & 7, kg = k0 + c * 4;
                int gn = n0 + r;
                uint32_t dB = Bu + (uint32_t)(r * LDS_STRIDE + c * 4) * 4u;
                if (gn < Nt) {
                    CPA16(dB, Bexp + (size_t)gn * Kdim + kg);
                } else {
                    *(float4*)(Bb + r * LDS_STRIDE + c * 4) = make_float4(0, 0, 0, 0);
                }
            }
        } else {
            for (int u = tid; u < 128 * 16; u += 256) {
                int r = u >> 4, c = u & 15, kg = k0 + c * 2;
                int gm = m0 + r;
                uint32_t dA = Au + (uint32_t)(r * LDS_STRIDE + c * 2) * 4u;
                if (gm < cnt && kg < Kdim) {
                    int pr = rows[gm];
                    int rr = row_shift ? (pr >> 1) : pr;
                    CPA8(dA, A + (size_t)rr * Kdim + kg);
                } else {
                    *(float2*)(Ab + r * LDS_STRIDE + c * 2) = make_float2(0, 0);
                }
            }
            for (int u = tid; u < 256 * 16; u += 256) {
                int r = u >> 4, c = u & 15, kg = k0 + c * 2;
                int gn = n0 + r;
                uint32_t dB = Bu + (uint32_t)(r * LDS_STRIDE + c * 2) * 4u;
                if (gn < Nt && kg < Kdim) {
                    CPA8(dB, Bexp + (size_t)gn * Kdim + kg);
                } else {
                    *(float2*)(Bb + r * LDS_STRIDE + c * 2) = make_float2(0, 0);
                }
            }
        }
    };

    // warp layout: 2 (m) x 4 (n); warp tile 64 x 64
    int wy = wid >> 2, wx = wid & 3;
    int mw = wy * 64, nw = wx * 64;
    int lr = lane >> 2, lc = lane & 3;

    float acc[4][8][4];
#pragma unroll
    for (int i = 0; i < 4; i++)
#pragma unroll
        for (int j = 0; j < 8; j++)
#pragma unroll
            for (int q = 0; q < 4; q++) acc[i][j][q] = 0.f;

    // prologue: stages 0 and 1
    load_tile(0, 0);
    CPA_COMMIT();
    if (nch > 1) load_tile(1, 1);
    CPA_COMMIT();

    for (int it = 0; it < nch; it++) {
        CPA_WAIT(1);          // chunk `it` resident (≤1 newer group pending)
        __syncthreads();      // single barrier: also fences stage (it-1) reads

        // prefetch chunk it+2 into stage (it+2)%3 (== (it-1)%3, safe post-barrier)
        if (it + 2 < nch) load_tile(it + 2, (it + 2) % NSTAGE);
        CPA_COMMIT();

        const float* As = sm + (it % NSTAGE) * STAGE_F;
        const float* Bs = As + A_TILE_F;
#pragma unroll
        for (int ks = 0; ks < BK; ks += 16) {
            uint32_t af[4][4], bf[8][2];
#pragma unroll
            for (int mt = 0; mt < 4; mt++) {
                const float* p = As + (mw + mt * 16 + lr) * LDS_STRIDE + ks + 2 * lc;
                float2 v0 = *(const float2*)(p);
                float2 v1 = *(const float2*)(p + 8 * LDS_STRIDE);
                float2 v2 = *(const float2*)(p + 8);
                float2 v3 = *(const float2*)(p + 8 * LDS_STRIDE + 8);
                af[mt][0] = packbf(v0.x, v0.y);
                af[mt][1] = packbf(v1.x, v1.y);
                af[mt][2] = packbf(v2.x, v2.y);
                af[mt][3] = packbf(v3.x, v3.y);
            }
#pragma unroll
            for (int nt = 0; nt < 8; nt++) {
                const float* q = Bs + (nw + nt * 8 + lr) * LDS_STRIDE + ks + 2 * lc;
                float2 u0 = *(const float2*)(q);
                float2 u1 = *(const float2*)(q + 8);
                bf[nt][0] = packbf(u0.x, u0.y);
                bf[nt][1] = packbf(u1.x, u1.y);
            }
#pragma unroll
            for (int mt = 0; mt < 4; mt++)
#pragma unroll
                for (int nt = 0; nt < 8; nt++)
                    mma_bf16(acc[mt][nt], af[mt], bf[nt]);
        }
    }

    __syncthreads();

    // ---- epilogue: scatter with gather row-mapping, bias, residual ----
    const float* bb = bias ? bias + (size_t)e * Nt : nullptr;
#pragma unroll
    for (int mt = 0; mt < 4; mt++) {
#pragma unroll
        for (int half = 0; half < 2; half++) {
            int rg = m0 + mw + mt * 16 + lr + half * 8;
            if (rg >= cnt) continue;
            int pair = rows[rg];
            size_t obase = (size_t)pair * Nt;
            const float* rr = resid ? resid + (size_t)(pair >> 1) * Nt : nullptr;
#pragma unroll
            for (int nt = 0; nt < 8; nt++) {
                int cg = n0 + nw + nt * 8 + 2 * lc;
#pragma unroll
                for (int q = 0; q < 2; q++) {
                    int col = cg + q;
                    if (col >= Nt) continue;
                    float v = acc[mt][nt][half * 2 + q];
                    if (bb) v += bb[col];
                    if (rr) v += rr[col];
                    Out[obase + col] = v;
                }
            }
        }
    }
}

// ------------------------- SwiGLU (exact GELU) -------------------------
__global__ void swiglu_kernel() {
    size_t i = (size_t)blockIdx.x * blockDim.x + threadIdx.x;
    const size_t total = (size_t)NPAIR * DFF_;
    if (i >= total) return;
    size_t p = i / DFF_;
    int    j = (int)(i % DFF_);
    float h = g_up[p * DFF2_ + j];
    float g = g_up[p * DFF2_ + DFF_ + j];
    float ge = 0.5f * g * (1.f + erff(g * 0.70710678118654752440f));
    g_h1[i] = h * ge;
}

// ------------------------- online logsumexp over vocab (single pass) ---------
__global__ void lse_kernel() {
    int p = blockIdx.x;
    const float* l = g_logits + (size_t)p * VOCAB_;
    int tid = threadIdx.x;
    float m = -INFINITY, s = 0.f;
    for (int v = tid; v < VOCAB_; v += 256) {
        float xv = l[v];
        if (xv > m) { s = s * expf(m - xv) + 1.f; m = xv; }
        else        { s += expf(xv - m); }
    }
    __shared__ float rm[256], rs[256];
    rm[tid] = m; rs[tid] = s;
    __syncthreads();
    for (int st = 128; st > 0; st >>= 1) {
        if (tid < st) {
            float m2 = rm[tid + st], s2 = rs[tid + st];
            float mm = fmaxf(rm[tid], m2);
            rs[tid] = rs[tid] * expf(rm[tid] - mm) + s2 * expf(m2 - mm);
            rm[tid] = mm;
        }
        __syncthreads();
    }
    if (tid == 0) g_lse[p] = rm[0] + logf(rs[0]);
}

// ------------------------- combine two experts per token ---------------------
__global__ void combine_kernel(float* __restrict__ out) {
    size_t idx = (size_t)blockIdx.x * blockDim.x + threadIdx.x;
    const size_t total = (size_t)S_ * VOCAB_;
    if (idx >= total) return;
    int s = (int)(idx / VOCAB_);
    int v = (int)(idx % VOCAB_);
    int p0 = 2 * s, p1 = 2 * s + 1;
    float a0 = g_logits[(size_t)p0 * VOCAB_ + v] + g_gate[p0] - g_lse[p0];
    float a1 = g_logits[(size_t)p1 * VOCAB_ + v] + g_gate[p1] - g_lse[p1];
    float m = fmaxf(a0, a1);
    out[idx] = m + logf(expf(a0 - m) + expf(a1 - m));
}

// ------------------------- launch -------------------------
extern "C" void kernel_launch(void* const* d_in, const int* in_sizes, int n_in,
                              void* d_out, int out_size) {
    const float *x = nullptr, *Wr = nullptr, *Wup = nullptr,
                *bup = nullptr, *Wdown = nullptr, *Wproj = nullptr;
    for (int i = 0; i < n_in; i++) {
        const float* p = (const float*)d_in[i];
        switch (in_sizes[i]) {
            case S_ * DIM_:            x     = p; break;
            case E_ * DIM_:            Wr    = p; break;
            case E_ * DFF2_ * DIM_:    Wup   = p; break;
            case E_ * DFF2_:           bup   = p; break;
            case E_ * DIM_ * DFF_:     Wdown = p; break;
            case E_ * VOCAB_ * DIM_:   Wproj = p; break;
        }
    }
    if (!x)     x     = (const float*)d_in[0];
    if (!Wr)    Wr    = (const float*)d_in[1];
    if (!Wup)   Wup   = (const float*)d_in[2];
    if (!bup)   bup   = (const float*)d_in[3];
    if (!Wdown) Wdown = (const float*)d_in[4];
    if (!Wproj) Wproj = (const float*)d_in[5];
    float* out = (float*)d_out;

    cudaFuncSetAttribute(gemm_tc_kernel,
                         cudaFuncAttributeMaxDynamicSharedMemorySize, GEMM_SMEM);

    router_kernel<<<S_, 256>>>(x, Wr);
    group_kernel<<<1, 256>>>();

    {   // up: g_up = x_g @ Wup[e]^T + bup[e]
        dim3 grid((DFF2_ + TN - 1) / TN, (NPAIR + TM - 1) / TM, E_);
        gemm_tc_kernel<<<grid, 256, GEMM_SMEM>>>(x, Wup, bup, nullptr,
                                                 0, 0, DIM_, DFF2_, 1);
    }
    {   // SwiGLU
        size_t total = (size_t)NPAIR * DFF_;
        swiglu_kernel<<<(int)((total + 255) / 256), 256>>>();
    }
    {   // down + residual: g_h2 = g_h1 @ Wdown[e]^T + x
        dim3 grid((DIM_ + TN - 1) / TN, (NPAIR + TM - 1) / TM, E_);
        gemm_tc_kernel<<<grid, 256, GEMM_SMEM>>>(nullptr, Wdown, nullptr, x,
                                                 1, 1, DFF_, DIM_, 0);
    }
    {   // proj: g_logits = g_h2 @ Wproj[e]^T
        dim3 grid((VOCAB_ + TN - 1) / TN, (NPAIR + TM - 1) / TM, E_);
        gemm_tc_kernel<<<grid, 256, GEMM_SMEM>>>(nullptr, Wproj, nullptr, nullptr,
                                                 2, 2, DIM_, VOCAB_, 0);
    }
    lse_kernel<<<NPAIR, 256>>>();
    {
        size_t total = (size_t)S_ * VOCAB_;
        combine_kernel<<<(int)((total + 255) / 256), 256>>>(out);
    }
}